// round 1
// baseline (speedup 1.0000x reference)
#include <cuda_runtime.h>

#define NN 4096
#define FIN 128
#define UNITS 64
#define HEADS 4
#define MAX_E 256   // max degree; Binomial(4096, 0.01) -> mean 41, P(deg>200) ~ 0

__device__ float g_x [NN * UNITS];
__device__ float g_e1[NN * HEADS];
__device__ float g_e2[NN * HEADS];
__device__ float g_S0[UNITS];

// ---------------------------------------------------------------------------
// Kernel 1: x = inputs @ w   ([4096,128] @ [128,64])
// 256 threads/block, 16 rows/block. 2x2 register tile per thread via float2.
// Also zeroes g_S0 (block 0) before k_aux accumulates into it.
// ---------------------------------------------------------------------------
__global__ __launch_bounds__(256) void k_xw(const float* __restrict__ inp,
                                            const float* __restrict__ w) {
    __shared__ float ws[FIN * UNITS];   // 32 KB
    __shared__ float is[16][FIN];       // 8 KB
    int t  = threadIdx.x;
    int r0 = blockIdx.x * 16;

    for (int i = t * 4; i < FIN * UNITS; i += 1024)
        *(float4*)&ws[i] = *(const float4*)&w[i];
    for (int i = t * 4; i < 16 * FIN; i += 1024)
        *(float4*)&is[0][i] = *(const float4*)&inp[r0 * FIN + i];
    if (blockIdx.x == 0 && t < UNITS) g_S0[t] = 0.0f;
    __syncthreads();

    int cp = t & 31;       // column pair 0..31 -> cols u, u+1
    int u  = cp * 2;
    int rg = t >> 5;       // 0..7 -> rows rg*2, rg*2+1
    const float* i0p = &is[rg * 2][0];
    const float* i1p = &is[rg * 2 + 1][0];
    float a00 = 0, a01 = 0, a10 = 0, a11 = 0;
#pragma unroll 8
    for (int k = 0; k < FIN; k++) {
        float2 wv = *(const float2*)&ws[k * UNITS + u];
        float i0 = i0p[k], i1 = i1p[k];
        a00 += i0 * wv.x; a01 += i0 * wv.y;
        a10 += i1 * wv.x; a11 += i1 * wv.y;
    }
    int row0 = r0 + rg * 2;
    float2 o0 = make_float2(a00, a01);
    float2 o1 = make_float2(a10, a11);
    *(float2*)&g_x[ row0      * UNITS + u] = o0;
    *(float2*)&g_x[(row0 + 1) * UNITS + u] = o1;
}

// ---------------------------------------------------------------------------
// Kernel 2: e1 = x@attn_w1, e2 = x@attn_w2, S0 = colsum(x)
// 32 blocks x 256 threads; 128 rows/block. x tile in smem (stride 65 = no
// bank conflicts). Each thread computes all 4 heads of one (row, matrix).
// ---------------------------------------------------------------------------
__global__ __launch_bounds__(256) void k_aux(const float* __restrict__ aw1,
                                             const float* __restrict__ aw2) {
    __shared__ float  xs[128 * 65];      // ~33.3 KB padded
    __shared__ float4 a1s[UNITS];
    __shared__ float4 a2s[UNITS];
    __shared__ float  cs[4][UNITS];
    int t  = threadIdx.x;
    int r0 = blockIdx.x * 128;

    for (int i = t; i < 128 * UNITS; i += 256) {
        int r = i >> 6, u = i & 63;
        xs[r * 65 + u] = g_x[(r0 + r) * UNITS + u];
    }
    if (t < UNITS)            a1s[t]      = ((const float4*)aw1)[t];
    else if (t < 2 * UNITS)   a2s[t - 64] = ((const float4*)aw2)[t - 64];
    __syncthreads();

    {   // e1/e2: thread -> (row = t>>1, matrix = t&1), 4-head accumulators
        int r = t >> 1, m = t & 1;
        const float4* aw = m ? a2s : a1s;
        float h0 = 0, h1 = 0, h2 = 0, h3 = 0;
#pragma unroll 8
        for (int u2 = 0; u2 < UNITS; u2++) {
            float  xv = xs[r * 65 + u2];
            float4 a  = aw[u2];
            h0 += xv * a.x; h1 += xv * a.y; h2 += xv * a.z; h3 += xv * a.w;
        }
        float4 e = make_float4(h0, h1, h2, h3);
        if (m) *(float4*)&g_e2[(r0 + r) * HEADS] = e;
        else   *(float4*)&g_e1[(r0 + r) * HEADS] = e;
    }
    {   // colsum partials
        int u = t & 63, q = t >> 6;
        float ps = 0;
#pragma unroll 8
        for (int r = q; r < 128; r += 4) ps += xs[r * 65 + u];
        cs[q][u] = ps;
    }
    __syncthreads();
    if (t < UNITS)
        atomicAdd(&g_S0[t], cs[0][t] + cs[1][t] + cs[2][t] + cs[3][t]);
}

// ---------------------------------------------------------------------------
// Kernel 3: per-row sparse softmax-aggregate.
// One block (256 thr) per row i:
//  1) float4 scan of adj row (512B/warp coalesced), shfl prefix-sum compaction
//     of edge indices into smem (deterministic order, no atomics)
//  2) weights ew[e][h] = exp(relu(e1[i,h]+e2[j,h])) computed once into smem
//  3) 4 groups x 64 lanes accumulate A[h][u] = sum_e ew*x[j,u], Ex[u] = sum x[j,u]
//  4) out[i,h,u] = relu((S0[u] - Ex[u] + A[h][u]) / (N - deg + sum_e ew[e][h]))
// ---------------------------------------------------------------------------
__global__ __launch_bounds__(256) void k_attn(const float* __restrict__ adj,
                                              float* __restrict__ out) {
    __shared__ int   ejs[MAX_E];
    __shared__ __align__(16) float ew[MAX_E][HEADS];
    __shared__ float pacc[4][HEADS][UNITS];
    __shared__ float pex[4][UNITS];
    __shared__ float sse[HEADS];
    __shared__ float exr[UNITS];
    __shared__ int   s_wtot[8], s_woff[8], s_deg;

    int t = threadIdx.x;
    int i = blockIdx.x;
    const float* arow = adj + (size_t)i * NN;

    // --- phase 1: scan + compact -------------------------------------------
    float4 v[4];
#pragma unroll
    for (int c = 0; c < 4; c++)
        v[c] = *(const float4*)&arow[c * 1024 + t * 4];
    int cnt = 0;
#pragma unroll
    for (int c = 0; c < 4; c++)
        cnt += (v[c].x != 0.0f) + (v[c].y != 0.0f) +
               (v[c].z != 0.0f) + (v[c].w != 0.0f);

    int lane = t & 31, wid = t >> 5;
    int incl = cnt;
#pragma unroll
    for (int d = 1; d < 32; d <<= 1) {
        int nv = __shfl_up_sync(0xffffffffu, incl, d);
        if (lane >= d) incl += nv;
    }
    if (lane == 31) s_wtot[wid] = incl;
    __syncthreads();
    if (t < 8) {
        int vv = s_wtot[t];
        int inc2 = vv;
#pragma unroll
        for (int d = 1; d < 8; d <<= 1) {
            int nv = __shfl_up_sync(0xffu, inc2, d);
            if (t >= d) inc2 += nv;
        }
        s_woff[t] = inc2 - vv;
        if (t == 7) s_deg = inc2;
    }
    __syncthreads();
    int off = s_woff[wid] + incl - cnt;
#pragma unroll
    for (int c = 0; c < 4; c++) {
        int jb = c * 1024 + t * 4;
        if (v[c].x != 0.0f) { if (off < MAX_E) ejs[off] = jb;     off++; }
        if (v[c].y != 0.0f) { if (off < MAX_E) ejs[off] = jb + 1; off++; }
        if (v[c].z != 0.0f) { if (off < MAX_E) ejs[off] = jb + 2; off++; }
        if (v[c].w != 0.0f) { if (off < MAX_E) ejs[off] = jb + 3; off++; }
    }
    __syncthreads();
    int deg = min(s_deg, MAX_E);

    // --- phase 2: edge weights ---------------------------------------------
    for (int idx = t; idx < deg * HEADS; idx += 256) {
        int e = idx >> 2, h = idx & 3;
        int j = ejs[e];
        float c = g_e1[i * HEADS + h] + g_e2[j * HEADS + h];
        ew[e][h] = __expf(fmaxf(c, 0.0f));
    }
    __syncthreads();

    // --- phase 3: accumulate -----------------------------------------------
    int u = t & 63, g = t >> 6;
    float a0 = 0, a1 = 0, a2 = 0, a3 = 0, ex = 0;
    for (int e = g; e < deg; e += 4) {
        int j = ejs[e];
        float  xj = g_x[j * UNITS + u];
        float4 wv = *(const float4*)&ew[e][0];
        ex += xj;
        a0 += wv.x * xj; a1 += wv.y * xj; a2 += wv.z * xj; a3 += wv.w * xj;
    }
    pacc[g][0][u] = a0; pacc[g][1][u] = a1;
    pacc[g][2][u] = a2; pacc[g][3][u] = a3;
    pex[g][u] = ex;
    __syncthreads();

    if (t < HEADS) {   // sum of exp weights per head
        float s0 = 0, s1 = 0, s2 = 0, s3 = 0;
        int e = 0;
        for (; e + 4 <= deg; e += 4) {
            s0 += ew[e][t]; s1 += ew[e + 1][t];
            s2 += ew[e + 2][t]; s3 += ew[e + 3][t];
        }
        for (; e < deg; e++) s0 += ew[e][t];
        sse[t] = s0 + s1 + s2 + s3;
    }
    if (t >= 64 && t < 128) {
        int uu = t - 64;
        exr[uu] = pex[0][uu] + pex[1][uu] + pex[2][uu] + pex[3][uu];
    }
    __syncthreads();

    // --- phase 4: finalize --------------------------------------------------
    float A  = pacc[0][g][u] + pacc[1][g][u] + pacc[2][g][u] + pacc[3][g][u];
    float Z  = (float)(NN - deg) + sse[g];
    float val = (g_S0[u] - exr[u] + A) / Z;
    out[(size_t)i * (HEADS * UNITS) + g * UNITS + u] = fmaxf(val, 0.0f);
}

// ---------------------------------------------------------------------------
extern "C" void kernel_launch(void* const* d_in, const int* in_sizes, int n_in,
                              void* d_out, int out_size) {
    const float* inp = (const float*)d_in[0];
    const float* adj = (const float*)d_in[1];
    const float* w   = (const float*)d_in[2];
    const float* aw1 = (const float*)d_in[3];
    const float* aw2 = (const float*)d_in[4];
    float* out = (float*)d_out;

    k_xw  <<<NN / 16,  256>>>(inp, w);
    k_aux <<<NN / 128, 256>>>(aw1, aw2);
    k_attn<<<NN,       256>>>(adj, out);
}

// round 2
// speedup vs baseline: 1.1298x; 1.1298x over previous
#include <cuda_runtime.h>

#define NN 4096
#define FIN 128
#define UNITS 64
#define HEADS 4
#define MAX_E 256
#define PRE_BLOCKS 128
#define ROWS_PB 32     // rows per k_pre block

__device__ float g_x  [NN * UNITS];
__device__ float g_e1 [NN * HEADS];
__device__ float g_e2 [NN * HEADS];
__device__ float g_S0 [UNITS];
__device__ float g_S0p[PRE_BLOCKS * UNITS];

// ---------------------------------------------------------------------------
// k_pre: fused  x = inp@w,  e1 = x@aw1,  e2 = x@aw2,  colsum partials.
// grid 128, block 256. 32 rows/block, thread tile 2 rows x 4 cols.
// w staged through smem in two 16KB halves (static smem < 48KB).
// ---------------------------------------------------------------------------
__global__ __launch_bounds__(256) void k_pre(const float* __restrict__ inp,
                                             const float* __restrict__ w,
                                             const float* __restrict__ aw1,
                                             const float* __restrict__ aw2) {
    __shared__ float ws[64 * UNITS];        // 16 KB (one K-half of w)
    __shared__ float is[ROWS_PB][132];      // 16.9 KB inp tile (padded)
    __shared__ float xs[ROWS_PB][68];       // 8.7 KB x tile (padded)
    __shared__ float awd[2][UNITS][HEADS];  // 2 KB

    int t  = threadIdx.x;
    int r0 = blockIdx.x * ROWS_PB;

    // load inp tile (coalesced float4)
    const float4* gi = (const float4*)(inp + (size_t)r0 * FIN);
#pragma unroll
    for (int i = 0; i < 4; i++) {
        int f = t + 256 * i;
        int r = f >> 5, kq = f & 31;
        *(float4*)&is[r][kq * 4] = gi[f];
    }
    if (t < 64)       *(float4*)&awd[0][t][0]      = ((const float4*)aw1)[t];
    else if (t < 128) *(float4*)&awd[1][t - 64][0] = ((const float4*)aw2)[t - 64];

    int rr = (t >> 4) * 2;       // rows rr, rr+1
    int cc = (t & 15) * 4;       // cols cc..cc+3
    float4 a0 = make_float4(0, 0, 0, 0);
    float4 a1 = make_float4(0, 0, 0, 0);

#pragma unroll
    for (int s = 0; s < 2; s++) {
        __syncthreads();                       // protect ws reuse / is ready
#pragma unroll
        for (int i = 0; i < 4; i++)
            ((float4*)ws)[t + 256 * i] = ((const float4*)(w + s * 64 * UNITS))[t + 256 * i];
        __syncthreads();
#pragma unroll 8
        for (int k2 = 0; k2 < 64; k2++) {
            float  i0 = is[rr][s * 64 + k2];
            float  i1 = is[rr + 1][s * 64 + k2];
            float4 wv = *(float4*)&ws[k2 * UNITS + cc];
            a0.x += i0 * wv.x; a0.y += i0 * wv.y; a0.z += i0 * wv.z; a0.w += i0 * wv.w;
            a1.x += i1 * wv.x; a1.y += i1 * wv.y; a1.z += i1 * wv.z; a1.w += i1 * wv.w;
        }
    }

    *(float4*)&g_x[(size_t)(r0 + rr)     * UNITS + cc] = a0;
    *(float4*)&g_x[(size_t)(r0 + rr + 1) * UNITS + cc] = a1;
    *(float4*)&xs[rr][cc]     = a0;
    *(float4*)&xs[rr + 1][cc] = a1;
    __syncthreads();

    {   // e1/e2: thread -> (row = t>>3, matrix m = (t>>2)&1, head h = t&3)
        int row = t >> 3, m = (t >> 2) & 1, h = t & 3;
        float e = 0;
#pragma unroll 16
        for (int u = 0; u < UNITS; u++) e += xs[row][u] * awd[m][u][h];
        if (m) g_e2[(r0 + row) * HEADS + h] = e;
        else   g_e1[(r0 + row) * HEADS + h] = e;
    }
    if (t < UNITS) {    // colsum partial for this block's 32 rows
        float s = 0;
#pragma unroll
        for (int r = 0; r < ROWS_PB; r++) s += xs[r][t];
        g_S0p[blockIdx.x * UNITS + t] = s;
    }
}

// ---------------------------------------------------------------------------
// k_s0: deterministic reduce of 128 colsum partials -> g_S0.  1 block.
// ---------------------------------------------------------------------------
__global__ __launch_bounds__(256) void k_s0() {
    __shared__ float cs[4][UNITS];
    int t = threadIdx.x;
    int u = t & 63, q = t >> 6;
    float s = 0;
#pragma unroll
    for (int b = q; b < PRE_BLOCKS; b += 4) s += g_S0p[b * UNITS + u];
    cs[q][u] = s;
    __syncthreads();
    if (t < UNITS) g_S0[t] = cs[0][t] + cs[1][t] + cs[2][t] + cs[3][t];
}

// ---------------------------------------------------------------------------
// k_attn: per-row sparse softmax-aggregate (one 256-thr block per row).
// ---------------------------------------------------------------------------
__global__ __launch_bounds__(256) void k_attn(const float* __restrict__ adj,
                                              float* __restrict__ out) {
    __shared__ int    ejs[MAX_E];
    __shared__ __align__(16) float ew[MAX_E][HEADS];
    __shared__ float  pacc[4][HEADS][UNITS];
    __shared__ float  pex[4][UNITS];
    __shared__ float  sse[HEADS];
    __shared__ float  exr[UNITS];
    __shared__ float4 s_e1;
    __shared__ int    s_wtot[8], s_woff[8], s_deg;

    int t = threadIdx.x;
    int i = blockIdx.x;
    const float* arow = adj + (size_t)i * NN;

    // --- phase 1: scan + deterministic compaction --------------------------
    float4 v[4];
#pragma unroll
    for (int c = 0; c < 4; c++)
        v[c] = *(const float4*)&arow[c * 1024 + t * 4];
    int cnt = 0;
#pragma unroll
    for (int c = 0; c < 4; c++)
        cnt += (v[c].x != 0.0f) + (v[c].y != 0.0f) +
               (v[c].z != 0.0f) + (v[c].w != 0.0f);

    int lane = t & 31, wid = t >> 5;
    int incl = cnt;
#pragma unroll
    for (int d = 1; d < 32; d <<= 1) {
        int nv = __shfl_up_sync(0xffffffffu, incl, d);
        if (lane >= d) incl += nv;
    }
    if (lane == 31) s_wtot[wid] = incl;
    __syncthreads();
    if (t < 8) {
        int vv = s_wtot[t];
        int inc2 = vv;
#pragma unroll
        for (int d = 1; d < 8; d <<= 1) {
            int nv = __shfl_up_sync(0xffu, inc2, d);
            if (t >= d) inc2 += nv;
        }
        s_woff[t] = inc2 - vv;
        if (t == 7) s_deg = inc2;
    }
    if (t == 32) s_e1 = *(const float4*)&g_e1[i * HEADS];
    __syncthreads();
    int off = s_woff[wid] + incl - cnt;
#pragma unroll
    for (int c = 0; c < 4; c++) {
        int jb = c * 1024 + t * 4;
        if (v[c].x != 0.0f) { if (off < MAX_E) ejs[off] = jb;     off++; }
        if (v[c].y != 0.0f) { if (off < MAX_E) ejs[off] = jb + 1; off++; }
        if (v[c].z != 0.0f) { if (off < MAX_E) ejs[off] = jb + 2; off++; }
        if (v[c].w != 0.0f) { if (off < MAX_E) ejs[off] = jb + 3; off++; }
    }
    __syncthreads();
    int deg = min(s_deg, MAX_E);

    // --- phase 2: one float4 e2 load + 4 exps per edge ----------------------
    float4 e1v = s_e1;
    for (int e = t; e < deg; e += 256) {
        int j = ejs[e];
        float4 e2v = *(const float4*)&g_e2[j * HEADS];
        float4 w4;
        w4.x = __expf(fmaxf(e1v.x + e2v.x, 0.0f));
        w4.y = __expf(fmaxf(e1v.y + e2v.y, 0.0f));
        w4.z = __expf(fmaxf(e1v.z + e2v.z, 0.0f));
        w4.w = __expf(fmaxf(e1v.w + e2v.w, 0.0f));
        *(float4*)&ew[e][0] = w4;
    }
    __syncthreads();

    // --- phase 3: accumulate ------------------------------------------------
    int u = t & 63, g = t >> 6;
    float a0 = 0, a1 = 0, a2 = 0, a3 = 0, ex = 0;
    for (int e = g; e < deg; e += 4) {
        int j = ejs[e];
        float  xj = g_x[j * UNITS + u];
        float4 wv = *(float4*)&ew[e][0];
        ex += xj;
        a0 += wv.x * xj; a1 += wv.y * xj; a2 += wv.z * xj; a3 += wv.w * xj;
    }
    pacc[g][0][u] = a0; pacc[g][1][u] = a1;
    pacc[g][2][u] = a2; pacc[g][3][u] = a3;
    pex[g][u] = ex;
    __syncthreads();

    if (t < 32) {   // warp-parallel per-head sum of exp weights
        int h = t & 3, es = t >> 2;      // 8 e-lanes per head
        float s = 0;
        for (int e = es; e < deg; e += 8) s += ew[e][h];
#pragma unroll
        for (int d = 16; d >= 4; d >>= 1)
            s += __shfl_down_sync(0xffffffffu, s, d);
        if (t < 4) sse[h] = s;
    }
    if (t >= 64 && t < 128) {
        int uu = t - 64;
        exr[uu] = pex[0][uu] + pex[1][uu] + pex[2][uu] + pex[3][uu];
    }
    __syncthreads();

    // --- phase 4: finalize --------------------------------------------------
    float A   = pacc[0][g][u] + pacc[1][g][u] + pacc[2][g][u] + pacc[3][g][u];
    float Z   = (float)(NN - deg) + sse[g];
    float val = (g_S0[u] - exr[u] + A) / Z;
    out[(size_t)i * (HEADS * UNITS) + g * UNITS + u] = fmaxf(val, 0.0f);
}

// ---------------------------------------------------------------------------
extern "C" void kernel_launch(void* const* d_in, const int* in_sizes, int n_in,
                              void* d_out, int out_size) {
    const float* inp = (const float*)d_in[0];
    const float* adj = (const float*)d_in[1];
    const float* w   = (const float*)d_in[2];
    const float* aw1 = (const float*)d_in[3];
    const float* aw2 = (const float*)d_in[4];
    float* out = (float*)d_out;

    k_pre <<<PRE_BLOCKS, 256>>>(inp, w, aw1, aw2);
    k_s0  <<<1, 256>>>();
    k_attn<<<NN, 256>>>(adj, out);
}

// round 3
// speedup vs baseline: 1.4298x; 1.2655x over previous
#include <cuda_runtime.h>

#define NN 4096
#define FIN 128
#define UNITS 64
#define HEADS 4
#define MAX_E 128          // Binomial(4096,0.01): mean 41, P(deg>128) ~ 0
#define PRE_BLOCKS 256
#define ROWS_PB 16

__device__ float g_x  [NN * UNITS];
__device__ float g_e1 [NN * HEADS];
__device__ float g_e2 [NN * HEADS];
__device__ float g_S0 [UNITS];
__device__ float g_S0p[PRE_BLOCKS * UNITS];
__device__ int   g_deg[NN];
__device__ int   g_ej [NN * MAX_E];
__device__ unsigned int g_ticket;

// ---------------------------------------------------------------------------
// k_pre: fused x = inp@w, e1/e2 = x@aw*, colsum partials + last-block S0.
// 256 blocks x 512 threads, 16 rows/block, 1 row x 2 cols per thread.
// ---------------------------------------------------------------------------
__global__ __launch_bounds__(512) void k_pre(const float* __restrict__ inp,
                                             const float* __restrict__ w,
                                             const float* __restrict__ aw1,
                                             const float* __restrict__ aw2) {
    __shared__ float ws[FIN * UNITS];        // 32 KB
    __shared__ float is[ROWS_PB][132];       // 8.25 KB
    __shared__ float xs[ROWS_PB][68];        // 4.25 KB (reused for S0 reduce)
    __shared__ float awd[2][UNITS][HEADS];   // 2 KB
    __shared__ int   s_last;

    int t  = threadIdx.x;
    int r0 = blockIdx.x * ROWS_PB;

    // stage inp tile (16x128) and w (128x64)
    {
        const float4* gi = (const float4*)(inp + (size_t)r0 * FIN);
        int r = t >> 5, kq = t & 31;
        *(float4*)&is[r][kq * 4] = gi[t];
#pragma unroll
        for (int i = 0; i < 4; i++)
            ((float4*)ws)[t + 512 * i] = ((const float4*)w)[t + 512 * i];
        if (t < 64)       *(float4*)&awd[0][t][0]      = ((const float4*)aw1)[t];
        else if (t < 128) *(float4*)&awd[1][t - 64][0] = ((const float4*)aw2)[t - 64];
    }
    __syncthreads();

    // GEMM: thread -> (row = t>>5, cols c..c+1)
    {
        int r = t >> 5;
        int c = (t & 31) * 2;
        float a0 = 0.0f, a1 = 0.0f;
#pragma unroll 8
        for (int k = 0; k < FIN; k++) {
            float  iv = is[r][k];                       // warp broadcast
            float2 wv = *(float2*)&ws[k * UNITS + c];   // conflict-free
            a0 += iv * wv.x; a1 += iv * wv.y;
        }
        float2 o = make_float2(a0, a1);
        *(float2*)&g_x[(size_t)(r0 + r) * UNITS + c] = o;
        *(float2*)&xs[r][c] = o;
    }
    __syncthreads();

    // e1/e2 (threads 0..127) and colsum partial (threads 128..191) in parallel
    if (t < 128) {
        int row = t >> 3, m = (t >> 2) & 1, h = t & 3;
        float e = 0.0f;
#pragma unroll 16
        for (int u = 0; u < UNITS; u++) e += xs[row][u] * awd[m][u][h];
        if (m) g_e2[(r0 + row) * HEADS + h] = e;
        else   g_e1[(r0 + row) * HEADS + h] = e;
    } else if (t < 192) {
        int u = t - 128;
        float s = 0.0f;
#pragma unroll
        for (int r = 0; r < ROWS_PB; r++) s += xs[r][u];
        g_S0p[blockIdx.x * UNITS + u] = s;
    }
    __syncthreads();

    // deterministic last-block S0 reduction
    if (t == 0) {
        __threadfence();
        s_last = (atomicAdd(&g_ticket, 1u) == PRE_BLOCKS - 1);
    }
    __syncthreads();
    if (s_last) {
        float* red = (float*)xs;
        int u = t & 63, q = t >> 6;
        float s = 0.0f;
#pragma unroll 4
        for (int b = q; b < PRE_BLOCKS; b += 8) s += g_S0p[b * UNITS + u];
        red[q * UNITS + u] = s;
        __syncthreads();
        if (t < UNITS) {
            float tot = 0.0f;
#pragma unroll
            for (int q2 = 0; q2 < 8; q2++) tot += red[q2 * UNITS + t];
            g_S0[t] = tot;
        }
        if (t == 64) g_ticket = 0u;
    }
}

// ---------------------------------------------------------------------------
// k_scan: per-row adjacency scan + deterministic compaction -> CSR.
// One 256-thr block per row; 4 float4 per thread, warp/block prefix sums.
// ---------------------------------------------------------------------------
__global__ __launch_bounds__(256) void k_scan(const float* __restrict__ adj) {
    __shared__ int s_wtot[8], s_woff[8], s_deg;

    int t = threadIdx.x;
    int i = blockIdx.x;
    const float* arow = adj + (size_t)i * NN;

    float4 v[4];
#pragma unroll
    for (int c = 0; c < 4; c++)
        v[c] = *(const float4*)&arow[c * 1024 + t * 4];
    int cnt = 0;
#pragma unroll
    for (int c = 0; c < 4; c++)
        cnt += (v[c].x != 0.0f) + (v[c].y != 0.0f) +
               (v[c].z != 0.0f) + (v[c].w != 0.0f);

    int lane = t & 31, wid = t >> 5;
    int incl = cnt;
#pragma unroll
    for (int d = 1; d < 32; d <<= 1) {
        int nv = __shfl_up_sync(0xffffffffu, incl, d);
        if (lane >= d) incl += nv;
    }
    if (lane == 31) s_wtot[wid] = incl;
    __syncthreads();
    if (t < 8) {
        int vv = s_wtot[t];
        int inc2 = vv;
#pragma unroll
        for (int d = 1; d < 8; d <<= 1) {
            int nv = __shfl_up_sync(0xffu, inc2, d);
            if (t >= d) inc2 += nv;
        }
        s_woff[t] = inc2 - vv;
        if (t == 7) s_deg = inc2;
    }
    __syncthreads();

    int off = s_woff[wid] + incl - cnt;
    int* ej = g_ej + i * MAX_E;
#pragma unroll
    for (int c = 0; c < 4; c++) {
        int jb = c * 1024 + t * 4;
        if (v[c].x != 0.0f) { if (off < MAX_E) ej[off] = jb;     off++; }
        if (v[c].y != 0.0f) { if (off < MAX_E) ej[off] = jb + 1; off++; }
        if (v[c].z != 0.0f) { if (off < MAX_E) ej[off] = jb + 2; off++; }
        if (v[c].w != 0.0f) { if (off < MAX_E) ej[off] = jb + 3; off++; }
    }
    if (t == 0) g_deg[i] = min(s_deg, MAX_E);
}

// ---------------------------------------------------------------------------
// k_agg: per-row softmax-aggregate from CSR. One 256-thr block per row.
// ---------------------------------------------------------------------------
__global__ __launch_bounds__(256) void k_agg(float* __restrict__ out) {
    __shared__ int    ejs[MAX_E];
    __shared__ __align__(16) float ew[MAX_E][HEADS];
    __shared__ float  pacc[4][HEADS][UNITS];
    __shared__ float  pex[4][UNITS];
    __shared__ float  sse[HEADS];
    __shared__ float  exr[UNITS];
    __shared__ float4 s_e1;

    int t = threadIdx.x;
    int i = blockIdx.x;
    int deg = g_deg[i];

    if (t < MAX_E && t < deg) ejs[t] = g_ej[i * MAX_E + t];
    if (t == 255) s_e1 = *(const float4*)&g_e1[i * HEADS];
    __syncthreads();

    // edge weights: one thread per edge (deg <= 128)
    if (t < deg) {
        int j = ejs[t];
        float4 e1v = s_e1;
        float4 e2v = *(const float4*)&g_e2[j * HEADS];
        float4 w4;
        w4.x = __expf(fmaxf(e1v.x + e2v.x, 0.0f));
        w4.y = __expf(fmaxf(e1v.y + e2v.y, 0.0f));
        w4.z = __expf(fmaxf(e1v.z + e2v.z, 0.0f));
        w4.w = __expf(fmaxf(e1v.w + e2v.w, 0.0f));
        *(float4*)&ew[t][0] = w4;
    }
    __syncthreads();

    // accumulate: 4 groups x 64 lanes over the edge list
    int u = t & 63, g = t >> 6;
    {
        float a0 = 0, a1 = 0, a2 = 0, a3 = 0, ex = 0;
        for (int e = g; e < deg; e += 4) {
            int j = ejs[e];
            float  xj = g_x[j * UNITS + u];      // coalesced 256B per group
            float4 wv = *(float4*)&ew[e][0];     // broadcast
            ex += xj;
            a0 += wv.x * xj; a1 += wv.y * xj; a2 += wv.z * xj; a3 += wv.w * xj;
        }
        pacc[g][0][u] = a0; pacc[g][1][u] = a1;
        pacc[g][2][u] = a2; pacc[g][3][u] = a3;
        pex[g][u] = ex;
    }
    __syncthreads();

    if (t < 32) {   // warp-parallel per-head exp-sum
        int h = t & 3, es = t >> 2;
        float s = 0.0f;
        for (int e = es; e < deg; e += 8) s += ew[e][h];
#pragma unroll
        for (int d = 16; d >= 4; d >>= 1)
            s += __shfl_down_sync(0xffffffffu, s, d);
        if (t < 4) sse[h] = s;
    }
    if (t >= 64 && t < 128) {
        int uu = t - 64;
        exr[uu] = pex[0][uu] + pex[1][uu] + pex[2][uu] + pex[3][uu];
    }
    __syncthreads();

    float A   = pacc[0][g][u] + pacc[1][g][u] + pacc[2][g][u] + pacc[3][g][u];
    float Z   = (float)(NN - deg) + sse[g];
    float val = (g_S0[u] - exr[u] + A) / Z;
    out[(size_t)i * (HEADS * UNITS) + t] = fmaxf(val, 0.0f);
}

// ---------------------------------------------------------------------------
extern "C" void kernel_launch(void* const* d_in, const int* in_sizes, int n_in,
                              void* d_out, int out_size) {
    const float* inp = (const float*)d_in[0];
    const float* adj = (const float*)d_in[1];
    const float* w   = (const float*)d_in[2];
    const float* aw1 = (const float*)d_in[3];
    const float* aw2 = (const float*)d_in[4];
    float* out = (float*)d_out;

    k_scan<<<NN, 256>>>(adj);
    k_pre <<<PRE_BLOCKS, 512>>>(inp, w, aw1, aw2);
    k_agg <<<NN, 256>>>(out);
}

// round 9
// speedup vs baseline: 1.7073x; 1.1941x over previous
#include <cuda_runtime.h>

#define NN 4096
#define FIN 128
#define UNITS 64
#define HEADS 4
#define MAX_E 128          // Binomial(4096,0.01): mean 41, P(deg>128) ~ 1e-20
#define PRE_B 256          // pre-lite blocks (16 rows each)
#define SCAN_B 2048        // scan blocks (2 rows each)

__device__ __align__(16) float g_x  [NN * UNITS];
__device__ __align__(16) float g_e1 [NN * HEADS];
__device__ __align__(16) float g_e2 [NN * HEADS];
__device__ __align__(16) float g_S0 [UNITS];
__device__ __align__(16) float g_S0p[PRE_B * UNITS];
__device__ __align__(16) int   g_deg[NN];
__device__ __align__(16) int   g_ej [NN * MAX_E];
__device__ unsigned int g_ticket;

// ---------------------------------------------------------------------------
// scan one adjacency row: count+compact nonzeros into g_ej[row], deterministic.
// ---------------------------------------------------------------------------
__device__ __forceinline__ void scan_one_row(const float* __restrict__ arow,
                                             int row, int t,
                                             int* s_wtot, int* s_woff, int* s_deg) {
    float4 v[4];
#pragma unroll
    for (int c = 0; c < 4; c++)
        v[c] = *(const float4*)&arow[c * 1024 + t * 4];
    int cnt = 0;
#pragma unroll
    for (int c = 0; c < 4; c++)
        cnt += (v[c].x != 0.0f) + (v[c].y != 0.0f) +
               (v[c].z != 0.0f) + (v[c].w != 0.0f);

    int lane = t & 31, wid = t >> 5;
    int incl = cnt;
#pragma unroll
    for (int d = 1; d < 32; d <<= 1) {
        int nv = __shfl_up_sync(0xffffffffu, incl, d);
        if (lane >= d) incl += nv;
    }
    if (lane == 31) s_wtot[wid] = incl;
    __syncthreads();
    if (t < 8) {
        int vv = s_wtot[t];
        int inc2 = vv;
#pragma unroll
        for (int d = 1; d < 8; d <<= 1) {
            int nv = __shfl_up_sync(0xffu, inc2, d);
            if (t >= d) inc2 += nv;
        }
        s_woff[t] = inc2 - vv;
        if (t == 7) *s_deg = inc2;
    }
    __syncthreads();

    int off = s_woff[wid] + incl - cnt;
    int* ej = g_ej + row * MAX_E;
#pragma unroll
    for (int c = 0; c < 4; c++) {
        int jb = c * 1024 + t * 4;
        if (v[c].x != 0.0f) { if (off < MAX_E) ej[off] = jb;     off++; }
        if (v[c].y != 0.0f) { if (off < MAX_E) ej[off] = jb + 1; off++; }
        if (v[c].z != 0.0f) { if (off < MAX_E) ej[off] = jb + 2; off++; }
        if (v[c].w != 0.0f) { if (off < MAX_E) ej[off] = jb + 3; off++; }
    }
    if (t == 0) g_deg[row] = min(*s_deg, MAX_E);
}

// ---------------------------------------------------------------------------
// k_main: heterogeneous grid.
//   blocks [0, PRE_B):            pre-lite (x = inp@w, e1/e2, S0) — w via L1
//   blocks [PRE_B, PRE_B+SCAN_B): scan 2 adjacency rows -> CSR
// Pre work hides in the scan's idle issue slots (scan is DRAM-bound).
// ---------------------------------------------------------------------------
__global__ __launch_bounds__(256) void k_main(const float* __restrict__ adj,
                                              const float* __restrict__ inp,
                                              const float* __restrict__ gw,
                                              const float* __restrict__ aw1,
                                              const float* __restrict__ aw2) {
    __shared__ __align__(16) float is[16][132];            // 8.25 KB inp tile
    __shared__ __align__(16) float xs[16][68];             // 4.25 KB x tile / S0 reduce
    __shared__ __align__(16) float awd[2][UNITS][HEADS];   // 2 KB
    __shared__ __align__(16) int   s_wtot[8];
    __shared__ __align__(16) int   s_woff[8];
    __shared__ int s_deg, s_last;

    int t = threadIdx.x;

    if (blockIdx.x >= PRE_B) {
        // ---------------- scan: 2 rows ------------------------------------
        int i0 = (blockIdx.x - PRE_B) * 2;
        scan_one_row(adj + (size_t)i0 * NN,       i0,     t, s_wtot, s_woff, &s_deg);
        __syncthreads();
        scan_one_row(adj + (size_t)(i0 + 1) * NN, i0 + 1, t, s_wtot, s_woff, &s_deg);
        return;
    }

    // ---------------- pre-lite: 16 rows ------------------------------------
    int b  = blockIdx.x;
    int r0 = b * 16;

    {   // stage inp tile (16 x 128) + attn weights
        const float4* gi = (const float4*)(inp + (size_t)r0 * FIN);
#pragma unroll
        for (int i = 0; i < 2; i++) {
            int f = t + 256 * i;
            *(float4*)&is[f >> 5][(f & 31) * 4] = gi[f];
        }
        if (t < 64)       *(float4*)&awd[0][t][0]      = ((const float4*)aw1)[t];
        else if (t < 128) *(float4*)&awd[1][t - 64][0] = ((const float4*)aw2)[t - 64];
    }
    __syncthreads();

    {   // GEMM: warp -> 2 rows, lane -> 2 cols.  w read via L1 (32KB, hot).
        int wd = t >> 5, lane = t & 31;
        int ra = wd * 2, c = lane * 2;
        float a00 = 0, a01 = 0, a10 = 0, a11 = 0;
#pragma unroll 8
        for (int k = 0; k < FIN; k++) {
            float2 wv = __ldg((const float2*)&gw[k * UNITS + c]);
            float  i0 = is[ra][k];
            float  i1 = is[ra + 1][k];
            a00 += i0 * wv.x; a01 += i0 * wv.y;
            a10 += i1 * wv.x; a11 += i1 * wv.y;
        }
        float2 o0 = make_float2(a00, a01);
        float2 o1 = make_float2(a10, a11);
        *(float2*)&g_x[(size_t)(r0 + ra)     * UNITS + c] = o0;
        *(float2*)&g_x[(size_t)(r0 + ra + 1) * UNITS + c] = o1;
        *(float2*)&xs[ra][c]     = o0;
        *(float2*)&xs[ra + 1][c] = o1;
    }
    __syncthreads();

    if (t < 128) {   // e1/e2: (row = t>>3, m = (t>>2)&1, h = t&3)
        int row = t >> 3, m = (t >> 2) & 1, h = t & 3;
        float e = 0.0f;
#pragma unroll 16
        for (int u = 0; u < UNITS; u++) e += xs[row][u] * awd[m][u][h];
        if (m) g_e2[(r0 + row) * HEADS + h] = e;
        else   g_e1[(r0 + row) * HEADS + h] = e;
    } else if (t < 192) {   // colsum partial
        int u = t - 128;
        float s = 0.0f;
#pragma unroll
        for (int r = 0; r < 16; r++) s += xs[r][u];
        g_S0p[b * UNITS + u] = s;
    }
    __syncthreads();

    if (t == 0) {
        __threadfence();
        s_last = (atomicAdd(&g_ticket, 1u) == PRE_B - 1);
    }
    __syncthreads();
    if (s_last) {   // deterministic final S0 reduce
        float* red = (float*)xs;
        int u = t & 63, q = t >> 6;
        float s = 0.0f;
#pragma unroll 4
        for (int bb = q; bb < PRE_B; bb += 4) s += g_S0p[bb * UNITS + u];
        red[q * UNITS + u] = s;
        __syncthreads();
        if (t < UNITS)
            g_S0[t] = red[t] + red[UNITS + t] + red[2 * UNITS + t] + red[3 * UNITS + t];
        if (t == 64) g_ticket = 0u;
    }
}

// ---------------------------------------------------------------------------
// k_agg: softmax-aggregate, 2 rows per block (grid 2048, 256 thr).
// groups: 0 = row0/even edges, 1 = row0/odd, 2 = row1/even, 3 = row1/odd.
// ---------------------------------------------------------------------------
__global__ __launch_bounds__(256) void k_agg(float* __restrict__ out) {
    __shared__ __align__(16) int    ejs[2][MAX_E];
    __shared__ __align__(16) float  ew[2][MAX_E][HEADS];
    __shared__ __align__(16) float  pacc[4][HEADS][UNITS];
    __shared__ __align__(16) float  pex[4][UNITS];
    __shared__ __align__(16) float  sse[2][HEADS];
    __shared__ __align__(16) float  exr[2][UNITS];
    __shared__ __align__(16) float4 s_e1[2];
    __shared__ int s_deg[2];

    int t  = threadIdx.x;
    int i0 = blockIdx.x * 2;

    {   // phase A: unconditional CSR load (1 edge slot per thread) + scalars
        int r = t >> 7, e = t & 127;
        ejs[r][e] = g_ej[(i0 + r) * MAX_E + e];
        if (t < 2)  s_deg[t] = g_deg[i0 + t];
        if (t >= 254) s_e1[t - 254] = *(const float4*)&g_e1[(i0 + t - 254) * HEADS];
    }
    __syncthreads();

    {   // phase B: edge weights (one thread per edge slot)
        int r = t >> 7, e = t & 127;
        if (e < s_deg[r]) {
            int j = ejs[r][e];
            float4 e1v = s_e1[r];
            float4 e2v = *(const float4*)&g_e2[j * HEADS];
            float4 w4;
            w4.x = __expf(fmaxf(e1v.x + e2v.x, 0.0f));
            w4.y = __expf(fmaxf(e1v.y + e2v.y, 0.0f));
            w4.z = __expf(fmaxf(e1v.z + e2v.z, 0.0f));
            w4.w = __expf(fmaxf(e1v.w + e2v.w, 0.0f));
            *(float4*)&ew[r][e][0] = w4;
        }
    }
    __syncthreads();

    int u = t & 63, g = t >> 6;
    {   // phase C: gather-accumulate
        int r = g >> 1, p = g & 1;
        int deg = s_deg[r];
        float a0 = 0, a1 = 0, a2 = 0, a3 = 0, ex = 0;
        for (int e = p; e < deg; e += 2) {
            int j = ejs[r][e];
            float  xj = g_x[j * UNITS + u];     // coalesced 256B per group
            float4 wv = *(float4*)&ew[r][e][0]; // smem broadcast
            ex += xj;
            a0 += wv.x * xj; a1 += wv.y * xj; a2 += wv.z * xj; a3 += wv.w * xj;
        }
        pacc[g][0][u] = a0; pacc[g][1][u] = a1;
        pacc[g][2][u] = a2; pacc[g][3][u] = a3;
        pex[g][u] = ex;
    }
    __syncthreads();

    if (t < 64) {   // per-row, per-head exp-sums: warp r handles row r
        int r = t >> 5, lane = t & 31;
        int h = lane & 3, es = lane >> 2;     // 8 strides of edges per head
        int deg = s_deg[r];
        float s = 0.0f;
        for (int e = es; e < deg; e += 8) s += ew[r][e][h];
#pragma unroll
        for (int d = 16; d >= 4; d >>= 1)
            s += __shfl_down_sync(0xffffffffu, s, d);
        if (lane < 4) sse[r][h] = s;
    } else if (t >= 128) {   // exr: cross-parity reduce of pex
        int uu = t & 63, r = (t >> 6) & 1;
        exr[r][uu] = pex[2 * r][uu] + pex[2 * r + 1][uu];
    }
    __syncthreads();

    float S0 = g_S0[u];
#pragma unroll
    for (int r = 0; r < 2; r++) {
        float A   = pacc[2 * r][g][u] + pacc[2 * r + 1][g][u];
        float Z   = (float)(NN - s_deg[r]) + sse[r][g];
        float val = (S0 - exr[r][u] + A) / Z;
        out[(size_t)(i0 + r) * (HEADS * UNITS) + t] = fmaxf(val, 0.0f);
    }
}

// ---------------------------------------------------------------------------
extern "C" void kernel_launch(void* const* d_in, const int* in_sizes, int n_in,
                              void* d_out, int out_size) {
    const float* inp = (const float*)d_in[0];
    const float* adj = (const float*)d_in[1];
    const float* w   = (const float*)d_in[2];
    const float* aw1 = (const float*)d_in[3];
    const float* aw2 = (const float*)d_in[4];
    float* out = (float*)d_out;

    k_main<<<PRE_B + SCAN_B, 256>>>(adj, inp, w, aw1, aw2);
    k_agg <<<NN / 2, 256>>>(out);
}